// round 9
// baseline (speedup 1.0000x reference)
#include <cuda_runtime.h>
#include <cuda_fp16.h>
#include <mma.h>

#define NN  100000
#define EE  1600000
#define INF 128
#define HH  64
typedef unsigned long long u64;
using namespace nvcuda;

// ---- packed f32x2 ops (sm_103a) ----
#define FMA2(d,a,b,c) asm("fma.rn.f32x2 %0,%1,%2,%3;" : "=l"(d) : "l"(a), "l"(b), "l"(c))
#define ADD2(d,a,b)   asm("add.rn.f32x2 %0,%1,%2;"    : "=l"(d) : "l"(a), "l"(b))
#define MUL2(d,a,b)   asm("mul.rn.f32x2 %0,%1,%2;"    : "=l"(d) : "l"(a), "l"(b))
#define PACK2(d,x)    asm("mov.b64 %0,{%1,%1};" : "=l"(d) : "r"(__float_as_uint(x)))
#define PACKAB(d,a,b) asm("mov.b64 %0,{%1,%2};" : "=l"(d) : "r"(__float_as_uint(a)), "r"(__float_as_uint(b)))
#define UNPACK2(a,b,d) do { unsigned _ua,_ub; \
    asm("mov.b64 {%0,%1},%2;" : "=r"(_ua),"=r"(_ub) : "l"(d)); \
    a=__uint_as_float(_ua); b=__uint_as_float(_ub); } while(0)

__device__ __forceinline__ unsigned h2_to_u(__half2 h) {
    union { __half2 h; unsigned u; } c; c.h = h; return c.u;
}
__device__ __forceinline__ float2 u_to_f2(unsigned u) {
    union { unsigned u; __half2 h; } c; c.u = u; return __half22float2(c.h);
}

// ---------------- device scratch ----------------
__device__ float  g_ori[NN * HH];   // lin output fp32 (residual source)
__device__ __half g_th [NN * HH];   // conv input, fp16
__device__ __half g_xs [NN * HH];   // conv output, fp16 (pre-scaled by dinv[src])
__device__ float  g_dinv[NN];
__device__ int    g_cnt[NN];        // zero at load; k_fill drains it back to 0
__device__ int    g_ptr[NN + 1];
__device__ int    g_blk[128];
__device__ int    g_csr[EE];

// ---------------- CSR construction ----------------
__global__ void k_count(const int4* __restrict__ dst4, int e4) {
    int i = blockIdx.x * blockDim.x + threadIdx.x;
    if (i < e4) {
        int4 d = dst4[i];
        atomicAdd(&g_cnt[d.x], 1);
        atomicAdd(&g_cnt[d.y], 1);
        atomicAdd(&g_cnt[d.z], 1);
        atomicAdd(&g_cnt[d.w], 1);
    }
}

__global__ void k_scanA(int n) {
    __shared__ int s[1024];
    int tid = threadIdx.x;
    int i = blockIdx.x * 1024 + tid;
    int c = (i < n) ? g_cnt[i] : 0;
    s[tid] = c;
    __syncthreads();
    #pragma unroll
    for (int off = 1; off < 1024; off <<= 1) {
        int t = (tid >= off) ? s[tid - off] : 0;
        __syncthreads();
        s[tid] += t;
        __syncthreads();
    }
    if (i < n) {
        g_ptr[i] = s[tid] - c;
        g_dinv[i] = rsqrtf((float)(c + 1));
    }
    if (tid == 1023) g_blk[blockIdx.x] = s[1023];
}

__global__ void k_scanC(int nb, int n) {
    __shared__ int pref[128];
    int t = threadIdx.x;
    if (t < 128) pref[t] = (t < nb) ? g_blk[t] : 0;
    __syncthreads();
    #pragma unroll
    for (int off = 1; off < 128; off <<= 1) {
        int v = 0;
        if (t < 128 && t >= off) v = pref[t - off];
        __syncthreads();
        if (t < 128) pref[t] += v;
        __syncthreads();
    }
    int b = blockIdx.x;
    int base = (b == 0) ? 0 : pref[b - 1];
    int i = b * 1024 + t;
    if (i < n) g_ptr[i] += base;
    if (b == 0 && t == 0) g_ptr[n] = pref[127];
}

__global__ void k_fill(const int4* __restrict__ src4, const int4* __restrict__ dst4, int e4) {
    int i = blockIdx.x * blockDim.x + threadIdx.x;
    if (i < e4) {
        int4 s = src4[i];
        int4 d = dst4[i];
        g_csr[g_ptr[d.x] + atomicSub(&g_cnt[d.x], 1) - 1] = s.x;
        g_csr[g_ptr[d.y] + atomicSub(&g_cnt[d.y], 1) - 1] = s.y;
        g_csr[g_ptr[d.z] + atomicSub(&g_cnt[d.z], 1) - 1] = s.z;
        g_csr[g_ptr[d.w] + atomicSub(&g_cnt[d.w], 1) - 1] = s.w;
    }
}

// ------------- lin GEMM: ori = in[n,128] @ W[128,64] + b ; also t0 = fp16(ori) -------------
__global__ void __launch_bounds__(256, 3) k_lin(const float* __restrict__ A,
                                                const float* __restrict__ W,
                                                const float* __restrict__ bias,
                                                float* __restrict__ out,
                                                __half* __restrict__ outh, int n) {
    extern __shared__ char smem[];
    float* sA = (float*)smem;                         // [128][68]
    u64*   sW = (u64*)(smem + 128 * 68 * 4);          // [128][32]
    float* sB = (float*)(sW + INF * 32);              // [64]

    int t = threadIdx.x;
    int R0 = blockIdx.x * 128;

    {
        const float4* W4 = (const float4*)W;
        float4* sW4 = (float4*)sW;
        #pragma unroll
        for (int q = 0; q < 8; q++) sW4[t + q * 256] = W4[t + q * 256];
        if (t < HH) sB[t] = bias[t];
    }

    u64 acc[4][4];
    #pragma unroll
    for (int i = 0; i < 4; i++)
        #pragma unroll
        for (int j = 0; j < 4; j++) acc[i][j] = 0ull;

    int rbase = t & 31;
    int cp = (t >> 5) * 4;

    #pragma unroll
    for (int kc = 0; kc < 2; kc++) {
        __syncthreads();
        #pragma unroll
        for (int q = 0; q < 8; q++) {
            int idx = t + q * 256;
            int row = idx >> 4, kq = idx & 15;
            float4 v = make_float4(0.f, 0.f, 0.f, 0.f);
            if (R0 + row < n)
                v = *(const float4*)(A + (size_t)(R0 + row) * INF + kc * 64 + kq * 4);
            *(float4*)(sA + row * 68 + kq * 4) = v;
        }
        __syncthreads();

        #pragma unroll
        for (int k4 = 0; k4 < 16; k4++) {
            float4 av[4];
            #pragma unroll
            for (int i = 0; i < 4; i++)
                av[i] = *(const float4*)(sA + (rbase + 32 * i) * 68 + k4 * 4);
            #pragma unroll
            for (int kk = 0; kk < 4; kk++) {
                int k = kc * 64 + k4 * 4 + kk;
                ulonglong2 w0 = *(const ulonglong2*)(sW + k * 32 + cp);
                ulonglong2 w1 = *(const ulonglong2*)(sW + k * 32 + cp + 2);
                #pragma unroll
                for (int i = 0; i < 4; i++) {
                    float a = (kk == 0) ? av[i].x : (kk == 1) ? av[i].y
                            : (kk == 2) ? av[i].z : av[i].w;
                    u64 a2; PACK2(a2, a);
                    FMA2(acc[i][0], a2, w0.x, acc[i][0]);
                    FMA2(acc[i][1], a2, w0.y, acc[i][1]);
                    FMA2(acc[i][2], a2, w1.x, acc[i][2]);
                    FMA2(acc[i][3], a2, w1.y, acc[i][3]);
                }
            }
        }
    }

    #pragma unroll
    for (int i = 0; i < 4; i++) {
        int r = R0 + rbase + 32 * i;
        if (r >= n) continue;
        float f[8];
        #pragma unroll
        for (int j = 0; j < 4; j++) {
            u64 b2; PACKAB(b2, sB[2 * (cp + j)], sB[2 * (cp + j) + 1]);
            ADD2(acc[i][j], acc[i][j], b2);
            UNPACK2(f[2 * j], f[2 * j + 1], acc[i][j]);
        }
        ulonglong2* o = (ulonglong2*)((u64*)out + (size_t)r * 32 + cp);
        o[0] = make_ulonglong2(acc[i][0], acc[i][1]);
        o[1] = make_ulonglong2(acc[i][2], acc[i][3]);
        uint4 hv;
        hv.x = h2_to_u(__floats2half2_rn(f[0], f[1]));
        hv.y = h2_to_u(__floats2half2_rn(f[2], f[3]));
        hv.z = h2_to_u(__floats2half2_rn(f[4], f[5]));
        hv.w = h2_to_u(__floats2half2_rn(f[6], f[7]));
        *(uint4*)(outh + (size_t)r * HH + cp * 2) = hv;
    }
}

// ------------- conv GEMM via wmma: xs = (t[n,64]fp16 @ W[64,64]) * dinv[row] -------------
// 256 threads = 8 warps; each warp: one 16-row m-tile x 4 n-tiles, k = 4 x 16.
__global__ void __launch_bounds__(256) k_conv(const __half* __restrict__ T,
                                              const float* __restrict__ W,
                                              __half* __restrict__ xs, int n) {
    __shared__ __half sW[64 * 64];         // 8KB, row-major [k][n]
    __shared__ float  sO[8][16 * 16];      // 32KB, per-warp store tile

    int t = threadIdx.x, w = t >> 5, lane = t & 31;
    for (int i = t; i < 64 * 64; i += 256) sW[i] = __float2half(W[i]);
    __syncthreads();

    int row0 = blockIdx.x * 128 + w * 16;
    if (row0 >= n) return;   // n % 16 == 0 -> whole tile valid or invalid

    wmma::fragment<wmma::accumulator, 16, 16, 16, float> acc[4];
    #pragma unroll
    for (int nt = 0; nt < 4; nt++) wmma::fill_fragment(acc[nt], 0.0f);

    #pragma unroll
    for (int k = 0; k < 4; k++) {
        wmma::fragment<wmma::matrix_a, 16, 16, 16, __half, wmma::row_major> a;
        wmma::load_matrix_sync(a, T + (size_t)row0 * HH + k * 16, HH);
        #pragma unroll
        for (int nt = 0; nt < 4; nt++) {
            wmma::fragment<wmma::matrix_b, 16, 16, 16, __half, wmma::row_major> b;
            wmma::load_matrix_sync(b, sW + (k * 16) * 64 + nt * 16, 64);
            wmma::mma_sync(acc[nt], a, b, acc[nt]);
        }
    }

    int r = lane >> 1, c0 = (lane & 1) * 8;
    int row = row0 + r;
    float dv = g_dinv[row];
    #pragma unroll
    for (int nt = 0; nt < 4; nt++) {
        wmma::store_matrix_sync(&sO[w][0], acc[nt], 16, wmma::mem_row_major);
        __syncwarp();
        const float* p = &sO[w][r * 16 + c0];
        uint4 hv;
        hv.x = h2_to_u(__floats2half2_rn(p[0] * dv, p[1] * dv));
        hv.y = h2_to_u(__floats2half2_rn(p[2] * dv, p[3] * dv));
        hv.z = h2_to_u(__floats2half2_rn(p[4] * dv, p[5] * dv));
        hv.w = h2_to_u(__floats2half2_rn(p[6] * dv, p[7] * dv));
        *(uint4*)(xs + (size_t)row * HH + nt * 16 + c0) = hv;
        __syncwarp();
    }
}

// ---- aggregation over fp16 xs; FUSE: residual+LN+ReLU -> fp16 t ; else -> fp32 out ----
template<bool FUSE>
__global__ void k_agg(const __half* __restrict__ xs, const float* __restrict__ cb,
                      const float* __restrict__ ori,
                      const float* __restrict__ lw, const float* __restrict__ lb,
                      void* __restrict__ outp, int n) {
    int gi = blockIdx.x * blockDim.x + threadIdx.x;
    int row = gi >> 5, lane = gi & 31;
    if (row >= n) return;
    const unsigned* x2 = (const unsigned*)xs;
    float2 sf = u_to_f2(__ldg(x2 + (size_t)row * 32 + lane));
    float a0 = sf.x, a1 = sf.y;
    int e   = g_ptr[row];
    int end = g_ptr[row + 1];
    for (; e + 8 <= end; e += 8) {
        int s0 = g_csr[e],     s1 = g_csr[e + 1], s2 = g_csr[e + 2], s3 = g_csr[e + 3];
        int s4 = g_csr[e + 4], s5 = g_csr[e + 5], s6 = g_csr[e + 6], s7 = g_csr[e + 7];
        unsigned u0 = __ldg(x2 + (size_t)s0 * 32 + lane);
        unsigned u1 = __ldg(x2 + (size_t)s1 * 32 + lane);
        unsigned u2 = __ldg(x2 + (size_t)s2 * 32 + lane);
        unsigned u3 = __ldg(x2 + (size_t)s3 * 32 + lane);
        unsigned u4 = __ldg(x2 + (size_t)s4 * 32 + lane);
        unsigned u5 = __ldg(x2 + (size_t)s5 * 32 + lane);
        unsigned u6 = __ldg(x2 + (size_t)s6 * 32 + lane);
        unsigned u7 = __ldg(x2 + (size_t)s7 * 32 + lane);
        float2 f0 = u_to_f2(u0), f1 = u_to_f2(u1), f2 = u_to_f2(u2), f3 = u_to_f2(u3);
        float2 f4 = u_to_f2(u4), f5 = u_to_f2(u5), f6 = u_to_f2(u6), f7 = u_to_f2(u7);
        a0 += ((f0.x + f1.x) + (f2.x + f3.x)) + ((f4.x + f5.x) + (f6.x + f7.x));
        a1 += ((f0.y + f1.y) + (f2.y + f3.y)) + ((f4.y + f5.y) + (f6.y + f7.y));
    }
    if (e + 4 <= end) {
        int s0 = g_csr[e], s1 = g_csr[e + 1], s2 = g_csr[e + 2], s3 = g_csr[e + 3];
        unsigned u0 = __ldg(x2 + (size_t)s0 * 32 + lane);
        unsigned u1 = __ldg(x2 + (size_t)s1 * 32 + lane);
        unsigned u2 = __ldg(x2 + (size_t)s2 * 32 + lane);
        unsigned u3 = __ldg(x2 + (size_t)s3 * 32 + lane);
        float2 f0 = u_to_f2(u0), f1 = u_to_f2(u1), f2 = u_to_f2(u2), f3 = u_to_f2(u3);
        a0 += (f0.x + f1.x) + (f2.x + f3.x);
        a1 += (f0.y + f1.y) + (f2.y + f3.y);
        e += 4;
    }
    for (; e < end; e++) {
        float2 f = u_to_f2(__ldg(x2 + (size_t)g_csr[e] * 32 + lane));
        a0 += f.x;
        a1 += f.y;
    }
    float dv = g_dinv[row];
    float h0 = fmaf(a0, dv, cb[2 * lane]);
    float h1 = fmaf(a1, dv, cb[2 * lane + 1]);
    if (FUSE) {
        u64 ov = __ldg((const u64*)ori + (size_t)row * 32 + lane);
        float o0, o1; UNPACK2(o0, o1, ov);
        float x0 = h0 + o0, x1 = h1 + o1;
        float s = x0 + x1;
        #pragma unroll
        for (int off = 16; off; off >>= 1) s += __shfl_xor_sync(0xffffffffu, s, off);
        float mu = s * (1.0f / 64.0f);
        float d0 = x0 - mu, d1 = x1 - mu;
        float q = d0 * d0 + d1 * d1;
        #pragma unroll
        for (int off = 16; off; off >>= 1) q += __shfl_xor_sync(0xffffffffu, q, off);
        float r = rsqrtf(q * (1.0f / 64.0f) + 1e-5f);
        float y0 = fmaxf(fmaf(d0 * r, lw[2 * lane],     lb[2 * lane]),     0.f);
        float y1 = fmaxf(fmaf(d1 * r, lw[2 * lane + 1], lb[2 * lane + 1]), 0.f);
        ((unsigned*)outp)[(size_t)row * 32 + lane] = h2_to_u(__floats2half2_rn(y0, y1));
    } else {
        u64 o; PACKAB(o, h0, h1);
        ((u64*)outp)[(size_t)row * 32 + lane] = o;
    }
}

// ---------------- launcher ----------------
extern "C" void kernel_launch(void* const* d_in, const int* in_sizes, int n_in,
                              void* d_out, int out_size) {
    const float* in_feat = (const float*)d_in[0];
    const int*   ei      = (const int*)  d_in[1];
    const float* lin_w   = (const float*)d_in[2];
    const float* lin_b   = (const float*)d_in[3];
    const float* conv_w  = (const float*)d_in[4];
    const float* conv_b  = (const float*)d_in[5];
    const float* ln_w    = (const float*)d_in[6];
    const float* ln_b    = (const float*)d_in[7];
    float* out = (float*)d_out;

    int n = in_sizes[0] / INF;
    int e = in_sizes[1] / 2;
    const int* src = ei;
    const int* dst = ei + e;
    int e4 = e / 4;
    int nb = (n + 1023) / 1024;

    float  *p_ori;
    __half *p_th, *p_xs;
    cudaGetSymbolAddress((void**)&p_ori, g_ori);
    cudaGetSymbolAddress((void**)&p_th,  g_th);
    cudaGetSymbolAddress((void**)&p_xs,  g_xs);

    const int SM_LIN = 128 * 68 * 4 + INF * 32 * 8 + 64 * 4;  // 67840
    cudaFuncSetAttribute(k_lin, cudaFuncAttributeMaxDynamicSharedMemorySize, SM_LIN);

    int gmm = (n + 127) / 128;
    int gwp = (n * 32 + 255) / 256;

    // conv (wmma) at launch index 3 = ncu's captured slot.
    k_count<<<(e4 + 255) / 256, 256>>>((const int4*)dst, e4);                        // 0
    k_scanA<<<nb, 1024>>>(n);                                                        // 1
    k_lin <<<gmm, 256, SM_LIN>>>(in_feat, lin_w, lin_b, p_ori, p_th, n);             // 2
    k_conv<<<gmm, 256>>>(p_th, conv_w, p_xs, n);                                     // 3 <- profiled
    k_scanC<<<nb, 1024>>>(nb, n);                                                    // 4
    k_fill<<<(e4 + 255) / 256, 256>>>((const int4*)src, (const int4*)dst, e4);       // 5

    // prop 0
    k_agg<true><<<gwp, 256>>>(p_xs, conv_b, p_ori, ln_w + 1 * HH, ln_b + 1 * HH, p_th, n);
    // prop 1
    k_conv<<<gmm, 256>>>(p_th, conv_w, p_xs, n);
    k_agg<true><<<gwp, 256>>>(p_xs, conv_b, p_ori, ln_w + 2 * HH, ln_b + 2 * HH, p_th, n);
    // prop 2 (final -> d_out)
    k_conv<<<gmm, 256>>>(p_th, conv_w, p_xs, n);
    k_agg<false><<<gwp, 256>>>(p_xs, conv_b, nullptr, nullptr, nullptr, out, n);
}

// round 10
// speedup vs baseline: 1.1751x; 1.1751x over previous
#include <cuda_runtime.h>
#include <cuda_fp16.h>
#include <mma.h>

#define NN  100000
#define EE  1600000
#define INF 128
#define HH  64
typedef unsigned long long u64;
using namespace nvcuda;

// ---- packed f32x2 ops (sm_103a) ----
#define FMA2(d,a,b,c) asm("fma.rn.f32x2 %0,%1,%2,%3;" : "=l"(d) : "l"(a), "l"(b), "l"(c))
#define ADD2(d,a,b)   asm("add.rn.f32x2 %0,%1,%2;"    : "=l"(d) : "l"(a), "l"(b))
#define MUL2(d,a,b)   asm("mul.rn.f32x2 %0,%1,%2;"    : "=l"(d) : "l"(a), "l"(b))
#define PACK2(d,x)    asm("mov.b64 %0,{%1,%1};" : "=l"(d) : "r"(__float_as_uint(x)))
#define PACKAB(d,a,b) asm("mov.b64 %0,{%1,%2};" : "=l"(d) : "r"(__float_as_uint(a)), "r"(__float_as_uint(b)))
#define UNPACK2(a,b,d) do { unsigned _ua,_ub; \
    asm("mov.b64 {%0,%1},%2;" : "=r"(_ua),"=r"(_ub) : "l"(d)); \
    a=__uint_as_float(_ua); b=__uint_as_float(_ub); } while(0)

__device__ __forceinline__ unsigned h2_to_u(__half2 h) {
    union { __half2 h; unsigned u; } c; c.h = h; return c.u;
}
__device__ __forceinline__ float2 u_to_f2(unsigned u) {
    union { unsigned u; __half2 h; } c; c.u = u; return __half22float2(c.h);
}

// ---------------- device scratch ----------------
__device__ float  g_ori[NN * HH];   // lin output fp32 (residual source)
__device__ __half g_th [NN * HH];   // conv input, fp16
__device__ __half g_xs [NN * HH];   // conv output, fp16 (pre-scaled by dinv[src])
__device__ float  g_dinv[NN];
__device__ int    g_cnt[NN];        // zero at load; k_fill drains it back to 0
__device__ int    g_ptr[NN + 1];
__device__ int    g_blk[128];
__device__ int    g_csr[EE];

// ---------------- CSR construction ----------------
__global__ void k_count(const int4* __restrict__ dst4, int e4) {
    int i = blockIdx.x * blockDim.x + threadIdx.x;
    if (i < e4) {
        int4 d = dst4[i];
        atomicAdd(&g_cnt[d.x], 1);
        atomicAdd(&g_cnt[d.y], 1);
        atomicAdd(&g_cnt[d.z], 1);
        atomicAdd(&g_cnt[d.w], 1);
    }
}

__global__ void k_scanA(int n) {
    __shared__ int s[1024];
    int tid = threadIdx.x;
    int i = blockIdx.x * 1024 + tid;
    int c = (i < n) ? g_cnt[i] : 0;
    s[tid] = c;
    __syncthreads();
    #pragma unroll
    for (int off = 1; off < 1024; off <<= 1) {
        int t = (tid >= off) ? s[tid - off] : 0;
        __syncthreads();
        s[tid] += t;
        __syncthreads();
    }
    if (i < n) {
        g_ptr[i] = s[tid] - c;
        g_dinv[i] = rsqrtf((float)(c + 1));
    }
    if (tid == 1023) g_blk[blockIdx.x] = s[1023];
}

__global__ void k_scanC(int nb, int n) {
    __shared__ int pref[128];
    int t = threadIdx.x;
    if (t < 128) pref[t] = (t < nb) ? g_blk[t] : 0;
    __syncthreads();
    #pragma unroll
    for (int off = 1; off < 128; off <<= 1) {
        int v = 0;
        if (t < 128 && t >= off) v = pref[t - off];
        __syncthreads();
        if (t < 128) pref[t] += v;
        __syncthreads();
    }
    int b = blockIdx.x;
    int base = (b == 0) ? 0 : pref[b - 1];
    int i = b * 1024 + t;
    if (i < n) g_ptr[i] += base;
    if (b == 0 && t == 0) g_ptr[n] = pref[127];
}

__global__ void k_fill(const int4* __restrict__ src4, const int4* __restrict__ dst4, int e4) {
    int i = blockIdx.x * blockDim.x + threadIdx.x;
    if (i < e4) {
        int4 s = src4[i];
        int4 d = dst4[i];
        g_csr[g_ptr[d.x] + atomicSub(&g_cnt[d.x], 1) - 1] = s.x;
        g_csr[g_ptr[d.y] + atomicSub(&g_cnt[d.y], 1) - 1] = s.y;
        g_csr[g_ptr[d.z] + atomicSub(&g_cnt[d.z], 1) - 1] = s.z;
        g_csr[g_ptr[d.w] + atomicSub(&g_cnt[d.w], 1) - 1] = s.w;
    }
}

// ------------- lin GEMM: ori = in[n,128] @ W[128,64] + b ; also t0 = fp16(ori) -------------
__global__ void __launch_bounds__(256, 3) k_lin(const float* __restrict__ A,
                                                const float* __restrict__ W,
                                                const float* __restrict__ bias,
                                                float* __restrict__ out,
                                                __half* __restrict__ outh, int n) {
    extern __shared__ char smem[];
    float* sA = (float*)smem;                         // [128][68]
    u64*   sW = (u64*)(smem + 128 * 68 * 4);          // [128][32]
    float* sB = (float*)(sW + INF * 32);              // [64]

    int t = threadIdx.x;
    int R0 = blockIdx.x * 128;

    {
        const float4* W4 = (const float4*)W;
        float4* sW4 = (float4*)sW;
        #pragma unroll
        for (int q = 0; q < 8; q++) sW4[t + q * 256] = W4[t + q * 256];
        if (t < HH) sB[t] = bias[t];
    }

    u64 acc[4][4];
    #pragma unroll
    for (int i = 0; i < 4; i++)
        #pragma unroll
        for (int j = 0; j < 4; j++) acc[i][j] = 0ull;

    int rbase = t & 31;
    int cp = (t >> 5) * 4;

    #pragma unroll
    for (int kc = 0; kc < 2; kc++) {
        __syncthreads();
        #pragma unroll
        for (int q = 0; q < 8; q++) {
            int idx = t + q * 256;
            int row = idx >> 4, kq = idx & 15;
            float4 v = make_float4(0.f, 0.f, 0.f, 0.f);
            if (R0 + row < n)
                v = *(const float4*)(A + (size_t)(R0 + row) * INF + kc * 64 + kq * 4);
            *(float4*)(sA + row * 68 + kq * 4) = v;
        }
        __syncthreads();

        #pragma unroll
        for (int k4 = 0; k4 < 16; k4++) {
            float4 av[4];
            #pragma unroll
            for (int i = 0; i < 4; i++)
                av[i] = *(const float4*)(sA + (rbase + 32 * i) * 68 + k4 * 4);
            #pragma unroll
            for (int kk = 0; kk < 4; kk++) {
                int k = kc * 64 + k4 * 4 + kk;
                ulonglong2 w0 = *(const ulonglong2*)(sW + k * 32 + cp);
                ulonglong2 w1 = *(const ulonglong2*)(sW + k * 32 + cp + 2);
                #pragma unroll
                for (int i = 0; i < 4; i++) {
                    float a = (kk == 0) ? av[i].x : (kk == 1) ? av[i].y
                            : (kk == 2) ? av[i].z : av[i].w;
                    u64 a2; PACK2(a2, a);
                    FMA2(acc[i][0], a2, w0.x, acc[i][0]);
                    FMA2(acc[i][1], a2, w0.y, acc[i][1]);
                    FMA2(acc[i][2], a2, w1.x, acc[i][2]);
                    FMA2(acc[i][3], a2, w1.y, acc[i][3]);
                }
            }
        }
    }

    #pragma unroll
    for (int i = 0; i < 4; i++) {
        int r = R0 + rbase + 32 * i;
        if (r >= n) continue;
        float f[8];
        #pragma unroll
        for (int j = 0; j < 4; j++) {
            u64 b2; PACKAB(b2, sB[2 * (cp + j)], sB[2 * (cp + j) + 1]);
            ADD2(acc[i][j], acc[i][j], b2);
            UNPACK2(f[2 * j], f[2 * j + 1], acc[i][j]);
        }
        ulonglong2* o = (ulonglong2*)((u64*)out + (size_t)r * 32 + cp);
        o[0] = make_ulonglong2(acc[i][0], acc[i][1]);
        o[1] = make_ulonglong2(acc[i][2], acc[i][3]);
        uint4 hv;
        hv.x = h2_to_u(__floats2half2_rn(f[0], f[1]));
        hv.y = h2_to_u(__floats2half2_rn(f[2], f[3]));
        hv.z = h2_to_u(__floats2half2_rn(f[4], f[5]));
        hv.w = h2_to_u(__floats2half2_rn(f[6], f[7]));
        *(uint4*)(outh + (size_t)r * HH + cp * 2) = hv;
    }
}

// ------------- conv GEMM via wmma (smem-staged): xs = (t[n,64]h @ W[64,64]) * dinv -------------
// 256 threads = 8 warps; warp w owns rows [w*16, w*16+16) of the 128-row tile.
// sT/sW padded to stride 72 halves (144B) -> conflict-free LDSM.
// Epilogue: 4 n-tile accs -> one padded 16x68 fp32 tile per warp, 1 syncwarp, STG.128 out.
#define CV_SW   (64 * 72)                 // 9216 halves
#define CV_ST   (128 * 72)                // 9216 halves
#define CV_SO   (16 * 68)                 // 1088 floats per warp
#define CV_SMEM (CV_SW * 2 + CV_ST * 2 + 8 * CV_SO * 4)   // 62464 bytes

__global__ void __launch_bounds__(256) k_conv(const __half* __restrict__ T,
                                              const float* __restrict__ W,
                                              __half* __restrict__ xs, int n) {
    extern __shared__ char sm[];
    __half* sW = (__half*)sm;                         // [64][72]
    __half* sT = (__half*)(sm + CV_SW * 2);           // [128][72]
    float*  sO = (float*)(sm + CV_SW * 2 + CV_ST * 2);// [8][16*68]

    int t = threadIdx.x, w = t >> 5, lane = t & 31;
    int R0 = blockIdx.x * 128;

    // stage W (fp32 -> fp16), padded
    for (int i = t; i < 64 * 64; i += 256) {
        int k = i >> 6, j = i & 63;
        sW[k * 72 + j] = __float2half(W[i]);
    }
    // stage T tile coalesced: 128 rows x 64 halves = 1024 uint4
    #pragma unroll
    for (int q = 0; q < 4; q++) {
        int idx = t + q * 256;
        int row = idx >> 3, c8 = idx & 7;             // 8 uint4 per row
        uint4 v = make_uint4(0u, 0u, 0u, 0u);
        if (R0 + row < n)
            v = *(const uint4*)(T + (size_t)(R0 + row) * HH + c8 * 8);
        *(uint4*)(sT + row * 72 + c8 * 8) = v;
    }
    __syncthreads();

    int row0 = R0 + w * 16;
    if (row0 >= n) return;    // n % 16 == 0 -> tile fully valid or fully invalid

    wmma::fragment<wmma::accumulator, 16, 16, 16, float> acc[4];
    #pragma unroll
    for (int nt = 0; nt < 4; nt++) wmma::fill_fragment(acc[nt], 0.0f);

    #pragma unroll
    for (int k = 0; k < 4; k++) {
        wmma::fragment<wmma::matrix_a, 16, 16, 16, __half, wmma::row_major> a;
        wmma::load_matrix_sync(a, sT + (w * 16) * 72 + k * 16, 72);
        #pragma unroll
        for (int nt = 0; nt < 4; nt++) {
            wmma::fragment<wmma::matrix_b, 16, 16, 16, __half, wmma::row_major> b;
            wmma::load_matrix_sync(b, sW + (k * 16) * 72 + nt * 16, 72);
            wmma::mma_sync(acc[nt], a, b, acc[nt]);
        }
    }

    float* sOw = sO + w * CV_SO;
    #pragma unroll
    for (int nt = 0; nt < 4; nt++)
        wmma::store_matrix_sync(sOw + nt * 16, acc[nt], 68, wmma::mem_row_major);
    __syncwarp();

    // lane -> row = lane>>1, col half = (lane&1)*32
    int r = lane >> 1, ch = (lane & 1) * 32;
    int row = row0 + r;
    float dv = g_dinv[row];
    const float* p = sOw + r * 68 + ch;
    __half* o = xs + (size_t)row * HH + ch;
    #pragma unroll
    for (int j = 0; j < 4; j++) {
        uint4 hv;
        hv.x = h2_to_u(__floats2half2_rn(p[8*j + 0] * dv, p[8*j + 1] * dv));
        hv.y = h2_to_u(__floats2half2_rn(p[8*j + 2] * dv, p[8*j + 3] * dv));
        hv.z = h2_to_u(__floats2half2_rn(p[8*j + 4] * dv, p[8*j + 5] * dv));
        hv.w = h2_to_u(__floats2half2_rn(p[8*j + 6] * dv, p[8*j + 7] * dv));
        *(uint4*)(o + j * 8) = hv;
    }
}

// ---- aggregation over fp16 xs; FUSE: residual+LN+ReLU -> fp16 t ; else -> fp32 out ----
template<bool FUSE>
__global__ void k_agg(const __half* __restrict__ xs, const float* __restrict__ cb,
                      const float* __restrict__ ori,
                      const float* __restrict__ lw, const float* __restrict__ lb,
                      void* __restrict__ outp, int n) {
    int gi = blockIdx.x * blockDim.x + threadIdx.x;
    int row = gi >> 5, lane = gi & 31;
    if (row >= n) return;
    const unsigned* x2 = (const unsigned*)xs;
    float2 sf = u_to_f2(__ldg(x2 + (size_t)row * 32 + lane));
    float a0 = sf.x, a1 = sf.y;
    int e   = g_ptr[row];
    int end = g_ptr[row + 1];
    for (; e + 8 <= end; e += 8) {
        int s0 = g_csr[e],     s1 = g_csr[e + 1], s2 = g_csr[e + 2], s3 = g_csr[e + 3];
        int s4 = g_csr[e + 4], s5 = g_csr[e + 5], s6 = g_csr[e + 6], s7 = g_csr[e + 7];
        unsigned u0 = __ldg(x2 + (size_t)s0 * 32 + lane);
        unsigned u1 = __ldg(x2 + (size_t)s1 * 32 + lane);
        unsigned u2 = __ldg(x2 + (size_t)s2 * 32 + lane);
        unsigned u3 = __ldg(x2 + (size_t)s3 * 32 + lane);
        unsigned u4 = __ldg(x2 + (size_t)s4 * 32 + lane);
        unsigned u5 = __ldg(x2 + (size_t)s5 * 32 + lane);
        unsigned u6 = __ldg(x2 + (size_t)s6 * 32 + lane);
        unsigned u7 = __ldg(x2 + (size_t)s7 * 32 + lane);
        float2 f0 = u_to_f2(u0), f1 = u_to_f2(u1), f2 = u_to_f2(u2), f3 = u_to_f2(u3);
        float2 f4 = u_to_f2(u4), f5 = u_to_f2(u5), f6 = u_to_f2(u6), f7 = u_to_f2(u7);
        a0 += ((f0.x + f1.x) + (f2.x + f3.x)) + ((f4.x + f5.x) + (f6.x + f7.x));
        a1 += ((f0.y + f1.y) + (f2.y + f3.y)) + ((f4.y + f5.y) + (f6.y + f7.y));
    }
    if (e + 4 <= end) {
        int s0 = g_csr[e], s1 = g_csr[e + 1], s2 = g_csr[e + 2], s3 = g_csr[e + 3];
        unsigned u0 = __ldg(x2 + (size_t)s0 * 32 + lane);
        unsigned u1 = __ldg(x2 + (size_t)s1 * 32 + lane);
        unsigned u2 = __ldg(x2 + (size_t)s2 * 32 + lane);
        unsigned u3 = __ldg(x2 + (size_t)s3 * 32 + lane);
        float2 f0 = u_to_f2(u0), f1 = u_to_f2(u1), f2 = u_to_f2(u2), f3 = u_to_f2(u3);
        a0 += (f0.x + f1.x) + (f2.x + f3.x);
        a1 += (f0.y + f1.y) + (f2.y + f3.y);
        e += 4;
    }
    for (; e < end; e++) {
        float2 f = u_to_f2(__ldg(x2 + (size_t)g_csr[e] * 32 + lane));
        a0 += f.x;
        a1 += f.y;
    }
    float dv = g_dinv[row];
    float h0 = fmaf(a0, dv, cb[2 * lane]);
    float h1 = fmaf(a1, dv, cb[2 * lane + 1]);
    if (FUSE) {
        u64 ov = __ldg((const u64*)ori + (size_t)row * 32 + lane);
        float o0, o1; UNPACK2(o0, o1, ov);
        float x0 = h0 + o0, x1 = h1 + o1;
        float s = x0 + x1;
        #pragma unroll
        for (int off = 16; off; off >>= 1) s += __shfl_xor_sync(0xffffffffu, s, off);
        float mu = s * (1.0f / 64.0f);
        float d0 = x0 - mu, d1 = x1 - mu;
        float q = d0 * d0 + d1 * d1;
        #pragma unroll
        for (int off = 16; off; off >>= 1) q += __shfl_xor_sync(0xffffffffu, q, off);
        float r = rsqrtf(q * (1.0f / 64.0f) + 1e-5f);
        float y0 = fmaxf(fmaf(d0 * r, lw[2 * lane],     lb[2 * lane]),     0.f);
        float y1 = fmaxf(fmaf(d1 * r, lw[2 * lane + 1], lb[2 * lane + 1]), 0.f);
        ((unsigned*)outp)[(size_t)row * 32 + lane] = h2_to_u(__floats2half2_rn(y0, y1));
    } else {
        u64 o; PACKAB(o, h0, h1);
        ((u64*)outp)[(size_t)row * 32 + lane] = o;
    }
}

// ---------------- launcher ----------------
extern "C" void kernel_launch(void* const* d_in, const int* in_sizes, int n_in,
                              void* d_out, int out_size) {
    const float* in_feat = (const float*)d_in[0];
    const int*   ei      = (const int*)  d_in[1];
    const float* lin_w   = (const float*)d_in[2];
    const float* lin_b   = (const float*)d_in[3];
    const float* conv_w  = (const float*)d_in[4];
    const float* conv_b  = (const float*)d_in[5];
    const float* ln_w    = (const float*)d_in[6];
    const float* ln_b    = (const float*)d_in[7];
    float* out = (float*)d_out;

    int n = in_sizes[0] / INF;
    int e = in_sizes[1] / 2;
    const int* src = ei;
    const int* dst = ei + e;
    int e4 = e / 4;
    int nb = (n + 1023) / 1024;

    float  *p_ori;
    __half *p_th, *p_xs;
    cudaGetSymbolAddress((void**)&p_ori, g_ori);
    cudaGetSymbolAddress((void**)&p_th,  g_th);
    cudaGetSymbolAddress((void**)&p_xs,  g_xs);

    const int SM_LIN = 128 * 68 * 4 + INF * 32 * 8 + 64 * 4;  // 67840
    cudaFuncSetAttribute(k_lin,  cudaFuncAttributeMaxDynamicSharedMemorySize, SM_LIN);
    cudaFuncSetAttribute(k_conv, cudaFuncAttributeMaxDynamicSharedMemorySize, CV_SMEM);

    int gmm = (n + 127) / 128;
    int gwp = (n * 32 + 255) / 256;

    // conv (wmma) at launch index 3 = ncu's captured slot.
    k_count<<<(e4 + 255) / 256, 256>>>((const int4*)dst, e4);                        // 0
    k_scanA<<<nb, 1024>>>(n);                                                        // 1
    k_lin <<<gmm, 256, SM_LIN>>>(in_feat, lin_w, lin_b, p_ori, p_th, n);             // 2
    k_conv<<<gmm, 256, CV_SMEM>>>(p_th, conv_w, p_xs, n);                            // 3 <- profiled
    k_scanC<<<nb, 1024>>>(nb, n);                                                    // 4
    k_fill<<<(e4 + 255) / 256, 256>>>((const int4*)src, (const int4*)dst, e4);       // 5

    // prop 0
    k_agg<true><<<gwp, 256>>>(p_xs, conv_b, p_ori, ln_w + 1 * HH, ln_b + 1 * HH, p_th, n);
    // prop 1
    k_conv<<<gmm, 256, CV_SMEM>>>(p_th, conv_w, p_xs, n);
    k_agg<true><<<gwp, 256>>>(p_xs, conv_b, p_ori, ln_w + 2 * HH, ln_b + 2 * HH, p_th, n);
    // prop 2 (final -> d_out)
    k_conv<<<gmm, 256, CV_SMEM>>>(p_th, conv_w, p_xs, n);
    k_agg<false><<<gwp, 256>>>(p_xs, conv_b, nullptr, nullptr, nullptr, out, n);
}

// round 11
// speedup vs baseline: 1.2125x; 1.0318x over previous
#include <cuda_runtime.h>
#include <cuda_fp16.h>
#include <mma.h>

#define NN  100000
#define EE  1600000
#define INF 128
#define HH  64
typedef unsigned long long u64;
using namespace nvcuda;

#define PACKAB(d,a,b) asm("mov.b64 %0,{%1,%2};" : "=l"(d) : "r"(__float_as_uint(a)), "r"(__float_as_uint(b)))
#define UNPACK2(a,b,d) do { unsigned _ua,_ub; \
    asm("mov.b64 {%0,%1},%2;" : "=r"(_ua),"=r"(_ub) : "l"(d)); \
    a=__uint_as_float(_ua); b=__uint_as_float(_ub); } while(0)

__device__ __forceinline__ unsigned h2_to_u(__half2 h) {
    union { __half2 h; unsigned u; } c; c.h = h; return c.u;
}
__device__ __forceinline__ float2 u_to_f2(unsigned u) {
    union { unsigned u; __half2 h; } c; c.u = u; return __half22float2(c.h);
}

// ---------------- device scratch ----------------
__device__ float  g_ori[NN * HH];   // lin output fp32 (residual source)
__device__ __half g_th [NN * HH];   // conv input, fp16
__device__ __half g_xs [NN * HH];   // conv output, fp16 (pre-scaled by dinv[src])
__device__ float  g_dinv[NN];
__device__ int    g_cnt[NN];        // zero at load; k_fill drains it back to 0
__device__ int    g_ptr[NN + 1];
__device__ int    g_blk[128];
__device__ int    g_csr[EE];

// ---------------- CSR construction ----------------
__global__ void k_count(const int4* __restrict__ dst4, int e4) {
    int i = blockIdx.x * blockDim.x + threadIdx.x;
    if (i < e4) {
        int4 d = dst4[i];
        atomicAdd(&g_cnt[d.x], 1);
        atomicAdd(&g_cnt[d.y], 1);
        atomicAdd(&g_cnt[d.z], 1);
        atomicAdd(&g_cnt[d.w], 1);
    }
}

__global__ void k_scanA(int n) {
    __shared__ int s[1024];
    int tid = threadIdx.x;
    int i = blockIdx.x * 1024 + tid;
    int c = (i < n) ? g_cnt[i] : 0;
    s[tid] = c;
    __syncthreads();
    #pragma unroll
    for (int off = 1; off < 1024; off <<= 1) {
        int t = (tid >= off) ? s[tid - off] : 0;
        __syncthreads();
        s[tid] += t;
        __syncthreads();
    }
    if (i < n) {
        g_ptr[i] = s[tid] - c;
        g_dinv[i] = rsqrtf((float)(c + 1));
    }
    if (tid == 1023) g_blk[blockIdx.x] = s[1023];
}

__global__ void k_scanC(int nb, int n) {
    __shared__ int pref[128];
    int t = threadIdx.x;
    if (t < 128) pref[t] = (t < nb) ? g_blk[t] : 0;
    __syncthreads();
    #pragma unroll
    for (int off = 1; off < 128; off <<= 1) {
        int v = 0;
        if (t < 128 && t >= off) v = pref[t - off];
        __syncthreads();
        if (t < 128) pref[t] += v;
        __syncthreads();
    }
    int b = blockIdx.x;
    int base = (b == 0) ? 0 : pref[b - 1];
    int i = b * 1024 + t;
    if (i < n) g_ptr[i] += base;
    if (b == 0 && t == 0) g_ptr[n] = pref[127];
}

__global__ void k_fill(const int4* __restrict__ src4, const int4* __restrict__ dst4, int e4) {
    int i = blockIdx.x * blockDim.x + threadIdx.x;
    if (i < e4) {
        int4 s = src4[i];
        int4 d = dst4[i];
        g_csr[g_ptr[d.x] + atomicSub(&g_cnt[d.x], 1) - 1] = s.x;
        g_csr[g_ptr[d.y] + atomicSub(&g_cnt[d.y], 1) - 1] = s.y;
        g_csr[g_ptr[d.z] + atomicSub(&g_cnt[d.z], 1) - 1] = s.z;
        g_csr[g_ptr[d.w] + atomicSub(&g_cnt[d.w], 1) - 1] = s.w;
    }
}

// ------------- lin GEMM via wmma: ori = in[n,128] @ W[128,64] + b ; t0 = fp16(ori) -------------
// smem: sW[128][72]h @0 (18432B) | sA[128][136]h @18432 (34816B) | sB @53248 (256B)
// sO[8][16*68]f aliases [0,34816) after a phase sync. Total 53504B.
#define LN_SMEM (18432 + 34816 + 256)
__global__ void __launch_bounds__(256) k_lin(const float* __restrict__ A,
                                             const float* __restrict__ W,
                                             const float* __restrict__ bias,
                                             float* __restrict__ out,
                                             __half* __restrict__ outh, int n) {
    extern __shared__ char sm[];
    __half* sW = (__half*)sm;                       // [128][72]
    __half* sA = (__half*)(sm + 18432);             // [128][136]
    float*  sB = (float*)(sm + 53248);              // [64]
    float*  sO = (float*)sm;                        // [8][16*68] (phase 2)

    int t = threadIdx.x, w = t >> 5, lane = t & 31;
    int R0 = blockIdx.x * 128;

    // stage W fp32->fp16 (128x64), padded stride 72
    for (int i = t; i < 128 * 64; i += 256) {
        int k = i >> 6, j = i & 63;
        sW[k * 72 + j] = __float2half(W[i]);
    }
    // stage A fp32->fp16 (128x128), padded stride 136; coalesced float4 reads
    #pragma unroll
    for (int q = 0; q < 16; q++) {
        int idx = t + q * 256;
        int row = idx >> 5, c4 = idx & 31;
        float4 v = make_float4(0.f, 0.f, 0.f, 0.f);
        if (R0 + row < n)
            v = *(const float4*)(A + (size_t)(R0 + row) * INF + c4 * 4);
        unsigned u0 = h2_to_u(__floats2half2_rn(v.x, v.y));
        unsigned u1 = h2_to_u(__floats2half2_rn(v.z, v.w));
        *(uint2*)(sA + row * 136 + c4 * 4) = make_uint2(u0, u1);
    }
    if (t < HH) sB[t] = bias[t];
    __syncthreads();

    int row0 = R0 + w * 16;
    bool act = row0 < n;   // n % 16 == 0

    wmma::fragment<wmma::accumulator, 16, 16, 16, float> acc[4];
    if (act) {
        #pragma unroll
        for (int nt = 0; nt < 4; nt++) wmma::fill_fragment(acc[nt], 0.0f);
        #pragma unroll
        for (int k = 0; k < 8; k++) {
            wmma::fragment<wmma::matrix_a, 16, 16, 16, __half, wmma::row_major> a;
            wmma::load_matrix_sync(a, sA + (w * 16) * 136 + k * 16, 136);
            #pragma unroll
            for (int nt = 0; nt < 4; nt++) {
                wmma::fragment<wmma::matrix_b, 16, 16, 16, __half, wmma::row_major> b;
                wmma::load_matrix_sync(b, sW + (k * 16) * 72 + nt * 16, 72);
                wmma::mma_sync(acc[nt], a, b, acc[nt]);
            }
        }
    }
    __syncthreads();   // phase boundary: sW/sA dead, sO live

    if (act) {
        float* sOw = sO + w * (16 * 68);
        #pragma unroll
        for (int nt = 0; nt < 4; nt++)
            wmma::store_matrix_sync(sOw + nt * 16, acc[nt], 68, wmma::mem_row_major);
        __syncwarp();
        int r = lane >> 1, ch = (lane & 1) * 32;
        int row = row0 + r;
        const float* p = sOw + r * 68 + ch;
        float* o = out + (size_t)row * HH + ch;
        __half* oh = outh + (size_t)row * HH + ch;
        #pragma unroll
        for (int j = 0; j < 4; j++) {
            float f0 = p[8*j + 0] + sB[ch + 8*j + 0];
            float f1 = p[8*j + 1] + sB[ch + 8*j + 1];
            float f2 = p[8*j + 2] + sB[ch + 8*j + 2];
            float f3 = p[8*j + 3] + sB[ch + 8*j + 3];
            float f4 = p[8*j + 4] + sB[ch + 8*j + 4];
            float f5 = p[8*j + 5] + sB[ch + 8*j + 5];
            float f6 = p[8*j + 6] + sB[ch + 8*j + 6];
            float f7 = p[8*j + 7] + sB[ch + 8*j + 7];
            *(float4*)(o + 8*j)     = make_float4(f0, f1, f2, f3);
            *(float4*)(o + 8*j + 4) = make_float4(f4, f5, f6, f7);
            uint4 hv;
            hv.x = h2_to_u(__floats2half2_rn(f0, f1));
            hv.y = h2_to_u(__floats2half2_rn(f2, f3));
            hv.z = h2_to_u(__floats2half2_rn(f4, f5));
            hv.w = h2_to_u(__floats2half2_rn(f6, f7));
            *(uint4*)(oh + 8*j) = hv;
        }
    }
}

// ------------- conv GEMM via wmma: xs = (t[n,64]h @ W[64,64]) * dinv -------------
// smem: sW[64][72]h @0 (9216B) | sT[128][72]h @9216 (18432B); sO[8][16*68]f aliases [0,34816).
#define CV_SMEM 34816
__global__ void __launch_bounds__(256) k_conv(const __half* __restrict__ T,
                                              const float* __restrict__ W,
                                              __half* __restrict__ xs, int n) {
    extern __shared__ char sm[];
    __half* sW = (__half*)sm;                       // [64][72]
    __half* sT = (__half*)(sm + 9216);              // [128][72]
    float*  sO = (float*)sm;                        // [8][16*68] (phase 2)

    int t = threadIdx.x, w = t >> 5, lane = t & 31;
    int R0 = blockIdx.x * 128;

    for (int i = t; i < 64 * 64; i += 256) {
        int k = i >> 6, j = i & 63;
        sW[k * 72 + j] = __float2half(W[i]);
    }
    #pragma unroll
    for (int q = 0; q < 4; q++) {
        int idx = t + q * 256;
        int row = idx >> 3, c8 = idx & 7;
        uint4 v = make_uint4(0u, 0u, 0u, 0u);
        if (R0 + row < n)
            v = *(const uint4*)(T + (size_t)(R0 + row) * HH + c8 * 8);
        *(uint4*)(sT + row * 72 + c8 * 8) = v;
    }
    __syncthreads();

    int row0 = R0 + w * 16;
    bool act = row0 < n;

    wmma::fragment<wmma::accumulator, 16, 16, 16, float> acc[4];
    if (act) {
        #pragma unroll
        for (int nt = 0; nt < 4; nt++) wmma::fill_fragment(acc[nt], 0.0f);
        #pragma unroll
        for (int k = 0; k < 4; k++) {
            wmma::fragment<wmma::matrix_a, 16, 16, 16, __half, wmma::row_major> a;
            wmma::load_matrix_sync(a, sT + (w * 16) * 72 + k * 16, 72);
            #pragma unroll
            for (int nt = 0; nt < 4; nt++) {
                wmma::fragment<wmma::matrix_b, 16, 16, 16, __half, wmma::row_major> b;
                wmma::load_matrix_sync(b, sW + (k * 16) * 72 + nt * 16, 72);
                wmma::mma_sync(acc[nt], a, b, acc[nt]);
            }
        }
    }
    __syncthreads();   // phase boundary: sW/sT dead, sO live

    if (act) {
        float* sOw = sO + w * (16 * 68);
        #pragma unroll
        for (int nt = 0; nt < 4; nt++)
            wmma::store_matrix_sync(sOw + nt * 16, acc[nt], 68, wmma::mem_row_major);
        __syncwarp();
        int r = lane >> 1, ch = (lane & 1) * 32;
        int row = row0 + r;
        float dv = g_dinv[row];
        const float* p = sOw + r * 68 + ch;
        __half* o = xs + (size_t)row * HH + ch;
        #pragma unroll
        for (int j = 0; j < 4; j++) {
            uint4 hv;
            hv.x = h2_to_u(__floats2half2_rn(p[8*j + 0] * dv, p[8*j + 1] * dv));
            hv.y = h2_to_u(__floats2half2_rn(p[8*j + 2] * dv, p[8*j + 3] * dv));
            hv.z = h2_to_u(__floats2half2_rn(p[8*j + 4] * dv, p[8*j + 5] * dv));
            hv.w = h2_to_u(__floats2half2_rn(p[8*j + 6] * dv, p[8*j + 7] * dv));
            *(uint4*)(o + j * 8) = hv;
        }
    }
}

// ---- aggregation over fp16 xs; FUSE: residual+LN+ReLU -> fp16 t ; else -> fp32 out ----
template<bool FUSE>
__global__ void k_agg(const __half* __restrict__ xs, const float* __restrict__ cb,
                      const float* __restrict__ ori,
                      const float* __restrict__ lw, const float* __restrict__ lb,
                      void* __restrict__ outp, int n) {
    int gi = blockIdx.x * blockDim.x + threadIdx.x;
    int row = gi >> 5, lane = gi & 31;
    if (row >= n) return;
    const unsigned* x2 = (const unsigned*)xs;
    float2 sf = u_to_f2(__ldg(x2 + (size_t)row * 32 + lane));
    float a0 = sf.x, a1 = sf.y;
    int e   = g_ptr[row];
    int end = g_ptr[row + 1];
    for (; e + 8 <= end; e += 8) {
        int s0 = g_csr[e],     s1 = g_csr[e + 1], s2 = g_csr[e + 2], s3 = g_csr[e + 3];
        int s4 = g_csr[e + 4], s5 = g_csr[e + 5], s6 = g_csr[e + 6], s7 = g_csr[e + 7];
        unsigned u0 = __ldg(x2 + (size_t)s0 * 32 + lane);
        unsigned u1 = __ldg(x2 + (size_t)s1 * 32 + lane);
        unsigned u2 = __ldg(x2 + (size_t)s2 * 32 + lane);
        unsigned u3 = __ldg(x2 + (size_t)s3 * 32 + lane);
        unsigned u4 = __ldg(x2 + (size_t)s4 * 32 + lane);
        unsigned u5 = __ldg(x2 + (size_t)s5 * 32 + lane);
        unsigned u6 = __ldg(x2 + (size_t)s6 * 32 + lane);
        unsigned u7 = __ldg(x2 + (size_t)s7 * 32 + lane);
        float2 f0 = u_to_f2(u0), f1 = u_to_f2(u1), f2 = u_to_f2(u2), f3 = u_to_f2(u3);
        float2 f4 = u_to_f2(u4), f5 = u_to_f2(u5), f6 = u_to_f2(u6), f7 = u_to_f2(u7);
        a0 += ((f0.x + f1.x) + (f2.x + f3.x)) + ((f4.x + f5.x) + (f6.x + f7.x));
        a1 += ((f0.y + f1.y) + (f2.y + f3.y)) + ((f4.y + f5.y) + (f6.y + f7.y));
    }
    if (e + 4 <= end) {
        int s0 = g_csr[e], s1 = g_csr[e + 1], s2 = g_csr[e + 2], s3 = g_csr[e + 3];
        unsigned u0 = __ldg(x2 + (size_t)s0 * 32 + lane);
        unsigned u1 = __ldg(x2 + (size_t)s1 * 32 + lane);
        unsigned u2 = __ldg(x2 + (size_t)s2 * 32 + lane);
        unsigned u3 = __ldg(x2 + (size_t)s3 * 32 + lane);
        float2 f0 = u_to_f2(u0), f1 = u_to_f2(u1), f2 = u_to_f2(u2), f3 = u_to_f2(u3);
        a0 += (f0.x + f1.x) + (f2.x + f3.x);
        a1 += (f0.y + f1.y) + (f2.y + f3.y);
        e += 4;
    }
    for (; e < end; e++) {
        float2 f = u_to_f2(__ldg(x2 + (size_t)g_csr[e] * 32 + lane));
        a0 += f.x;
        a1 += f.y;
    }
    float dv = g_dinv[row];
    float h0 = fmaf(a0, dv, cb[2 * lane]);
    float h1 = fmaf(a1, dv, cb[2 * lane + 1]);
    if (FUSE) {
        u64 ov = __ldg((const u64*)ori + (size_t)row * 32 + lane);
        float o0, o1; UNPACK2(o0, o1, ov);
        float x0 = h0 + o0, x1 = h1 + o1;
        float s = x0 + x1;
        #pragma unroll
        for (int off = 16; off; off >>= 1) s += __shfl_xor_sync(0xffffffffu, s, off);
        float mu = s * (1.0f / 64.0f);
        float d0 = x0 - mu, d1 = x1 - mu;
        float q = d0 * d0 + d1 * d1;
        #pragma unroll
        for (int off = 16; off; off >>= 1) q += __shfl_xor_sync(0xffffffffu, q, off);
        float r = rsqrtf(q * (1.0f / 64.0f) + 1e-5f);
        float y0 = fmaxf(fmaf(d0 * r, lw[2 * lane],     lb[2 * lane]),     0.f);
        float y1 = fmaxf(fmaf(d1 * r, lw[2 * lane + 1], lb[2 * lane + 1]), 0.f);
        ((unsigned*)outp)[(size_t)row * 32 + lane] = h2_to_u(__floats2half2_rn(y0, y1));
    } else {
        u64 o; PACKAB(o, h0, h1);
        ((u64*)outp)[(size_t)row * 32 + lane] = o;
    }
}

// ---------------- launcher ----------------
extern "C" void kernel_launch(void* const* d_in, const int* in_sizes, int n_in,
                              void* d_out, int out_size) {
    const float* in_feat = (const float*)d_in[0];
    const int*   ei      = (const int*)  d_in[1];
    const float* lin_w   = (const float*)d_in[2];
    const float* lin_b   = (const float*)d_in[3];
    const float* conv_w  = (const float*)d_in[4];
    const float* conv_b  = (const float*)d_in[5];
    const float* ln_w    = (const float*)d_in[6];
    const float* ln_b    = (const float*)d_in[7];
    float* out = (float*)d_out;

    int n = in_sizes[0] / INF;
    int e = in_sizes[1] / 2;
    const int* src = ei;
    const int* dst = ei + e;
    int e4 = e / 4;
    int nb = (n + 1023) / 1024;

    float  *p_ori;
    __half *p_th, *p_xs;
    cudaGetSymbolAddress((void**)&p_ori, g_ori);
    cudaGetSymbolAddress((void**)&p_th,  g_th);
    cudaGetSymbolAddress((void**)&p_xs,  g_xs);

    cudaFuncSetAttribute(k_lin,  cudaFuncAttributeMaxDynamicSharedMemorySize, LN_SMEM);
    cudaFuncSetAttribute(k_conv, cudaFuncAttributeMaxDynamicSharedMemorySize, CV_SMEM);

    int gmm = (n + 127) / 128;
    int gwp = (n * 32 + 255) / 256;

    // conv (wmma) at launch index 3 = ncu's captured slot.
    k_count<<<(e4 + 255) / 256, 256>>>((const int4*)dst, e4);                        // 0
    k_scanA<<<nb, 1024>>>(n);                                                        // 1
    k_lin <<<gmm, 256, LN_SMEM>>>(in_feat, lin_w, lin_b, p_ori, p_th, n);            // 2
    k_conv<<<gmm, 256, CV_SMEM>>>(p_th, conv_w, p_xs, n);                            // 3 <- profiled
    k_scanC<<<nb, 1024>>>(nb, n);                                                    // 4
    k_fill<<<(e4 + 255) / 256, 256>>>((const int4*)src, (const int4*)dst, e4);       // 5

    // prop 0
    k_agg<true><<<gwp, 256>>>(p_xs, conv_b, p_ori, ln_w + 1 * HH, ln_b + 1 * HH, p_th, n);
    // prop 1
    k_conv<<<gmm, 256, CV_SMEM>>>(p_th, conv_w, p_xs, n);
    k_agg<true><<<gwp, 256>>>(p_xs, conv_b, p_ori, ln_w + 2 * HH, ln_b + 2 * HH, p_th, n);
    // prop 2 (final -> d_out)
    k_conv<<<gmm, 256, CV_SMEM>>>(p_th, conv_w, p_xs, n);
    k_agg<false><<<gwp, 256>>>(p_xs, conv_b, nullptr, nullptr, nullptr, out, n);
}